// round 5
// baseline (speedup 1.0000x reference)
#include <cuda_runtime.h>

#define NB 64
#define NM 80
#define NT 4000
#define NCH 40       // chunks per row
#define LCH 100      // chunk length (NT / NCH), multiple of 4
#define WARM 192     // warmup window; 0.95^192 ~ 5e-5

__device__ float g_gate[NB * NT];

__device__ __forceinline__ float clampf(float x, float lo, float hi) {
    return fminf(fmaxf(x, lo), hi);
}
__device__ __forceinline__ float sigmoidf(float x) {
    return 1.0f / (1.0f + __expf(-x));
}

// ---------------------------------------------------------------------------
// Kernel 1: spectral-flatness gate per (b, t). Thread handles 4 consecutive t.
// Geometric mean via 4 partial products of 20 channels each (underflow-safe).
// ---------------------------------------------------------------------------
__global__ void __launch_bounds__(128) gate_kernel(
    const float* __restrict__ mel,
    const float* __restrict__ gate_temp)
{
    int idx = blockIdx.x * blockDim.x + threadIdx.x;
    if (idx >= NB * (NT / 4)) return;
    int b  = idx / (NT / 4);
    int t4 = idx - b * (NT / 4);

    const float4* base = reinterpret_cast<const float4*>(mel) + (size_t)b * NM * (NT / 4) + t4;

    float sum[4]  = {0.f, 0.f, 0.f, 0.f};
    float low[4]  = {0.f, 0.f, 0.f, 0.f};
    float high[4] = {0.f, 0.f, 0.f, 0.f};
    float lp[4]   = {0.f, 0.f, 0.f, 0.f};

    #pragma unroll
    for (int g = 0; g < 4; ++g) {
        float p[4] = {1.f, 1.f, 1.f, 1.f};
        #pragma unroll
        for (int j = 0; j < 20; ++j) {
            const int m = g * 20 + j;
            float4 v = base[(size_t)m * (NT / 4)];
            float xv[4] = {v.x, v.y, v.z, v.w};
            #pragma unroll
            for (int k = 0; k < 4; ++k) {
                sum[k] += xv[k];
                p[k]   *= xv[k] + 1e-8f;
                if (m < 26)  low[k]  += xv[k];   // M//3 = 26
                if (m >= 53) high[k] += xv[k];   // 2*M//3 = 53 -> 27 channels
            }
        }
        #pragma unroll
        for (int k = 0; k < 4; ++k) lp[k] += __log2f(p[k]);
    }

    const float gt = gate_temp[0];
    float4 gout;
    float* go = &gout.x;
    #pragma unroll
    for (int k = 0; k < 4; ++k) {
        float arith = sum[k] * (1.0f / NM) + 1e-8f;
        float geo   = exp2f(lp[k] * (1.0f / NM));
        float sf    = clampf(__fdividef(geo, arith), 0.f, 1.f);
        float lo_   = low[k]  * (1.0f / 26.0f);
        float hi_   = high[k] * (1.0f / 27.0f);
        float tilt  = clampf(__fdividef(lo_, lo_ + hi_ + 1e-8f), 0.f, 1.f);
        float sfa   = sf + (1.0f - sf) * fmaxf(tilt - 0.6f, 0.f);
        go[k] = sigmoidf(gt * (sfa - 0.5f));
    }
    reinterpret_cast<float4*>(g_gate)[idx] = gout;
}

// ---------------------------------------------------------------------------
// Kernel 2: dual PCEN (IIR scan with decay-truncated warmup) + gated blend.
// One thread per (row, chunk). row = b*NM + m. Chunks covering t < WARM are
// exact; later chunks warm up over WARM preceding samples (err ~0.95^192~5e-5).
// ---------------------------------------------------------------------------
__global__ void __launch_bounds__(256) pcen_kernel(
    const float* __restrict__ mel,
    const float* __restrict__ ls_ns, const float* __restrict__ la_ns,
    const float* __restrict__ ld_ns, const float* __restrict__ lr_ns,
    const float* __restrict__ ls_st, const float* __restrict__ la_st,
    const float* __restrict__ ld_st, const float* __restrict__ lr_st,
    float* __restrict__ out)
{
    int tid = blockIdx.x * blockDim.x + threadIdx.x;
    if (tid >= NB * NM * NCH) return;
    int chunk = tid / (NB * NM);
    int row   = tid - chunk * (NB * NM);
    int b = row / NM;
    int m = row - b * NM;

    // Per-channel params (cheap: once per thread)
    const float s_ns  = clampf(sigmoidf(ls_ns[m]), 0.05f, 0.3f);
    const float a_ns  = 1.0f - s_ns;
    const float al_ns = clampf(sigmoidf(la_ns[m]), 0.9f, 0.999f);
    const float d_ns  = clampf(__expf(ld_ns[m]), 0.5f, 5.0f);
    const float r_ns  = clampf(sigmoidf(lr_ns[m]), 0.05f, 0.25f);
    const float dp_ns = __powf(d_ns, r_ns);

    const float s_st  = clampf(sigmoidf(ls_st[m]), 0.05f, 0.3f);
    const float a_st  = 1.0f - s_st;
    const float al_st = clampf(sigmoidf(la_st[m]), 0.9f, 0.999f);
    const float d_st  = clampf(__expf(ld_st[m]), 0.001f, 0.1f);
    const float r_st  = clampf(sigmoidf(lr_st[m]), 0.05f, 0.25f);
    const float dp_st = __powf(d_st, r_st);

    const float* x  = mel + (size_t)row * NT;
    const float* gp = g_gate + (size_t)b * NT;
    float* o        = out + (size_t)row * NT;

    const int t0 = chunk * LCH;
    int tw = t0 - WARM;
    if (tw < 0) tw = 0;

    float sm_ns = x[tw];
    float sm_st = sm_ns;

    // Warmup: recurrence only (reads are L2-hot; early chunks are exact)
    for (int t = tw; t < t0; t += 4) {
        float4 v = *reinterpret_cast<const float4*>(x + t);
        sm_ns = fmaf(a_ns, sm_ns, s_ns * v.x); sm_st = fmaf(a_st, sm_st, s_st * v.x);
        sm_ns = fmaf(a_ns, sm_ns, s_ns * v.y); sm_st = fmaf(a_st, sm_st, s_st * v.y);
        sm_ns = fmaf(a_ns, sm_ns, s_ns * v.z); sm_st = fmaf(a_st, sm_st, s_st * v.z);
        sm_ns = fmaf(a_ns, sm_ns, s_ns * v.w); sm_st = fmaf(a_st, sm_st, s_st * v.w);
    }

#define PCEN_STEP(xx, gg, oo) do {                                     \
        sm_ns = fmaf(a_ns, sm_ns, s_ns * (xx));                        \
        sm_st = fmaf(a_st, sm_st, s_st * (xx));                        \
        float gn = __powf(1e-6f + sm_ns, -al_ns);                      \
        float on = __powf(fmaf((xx), gn, d_ns), r_ns) - dp_ns;         \
        float gs = __powf(1e-6f + sm_st, -al_st);                      \
        float os = __powf(fmaf((xx), gs, d_st), r_st) - dp_st;         \
        (oo) = fmaf((gg), os - on, on);                                \
    } while (0)

    for (int t = t0; t < t0 + LCH; t += 4) {
        float4 v = *reinterpret_cast<const float4*>(x + t);
        float4 g = *reinterpret_cast<const float4*>(gp + t);
        float4 ov;
        PCEN_STEP(v.x, g.x, ov.x);
        PCEN_STEP(v.y, g.y, ov.y);
        PCEN_STEP(v.z, g.z, ov.z);
        PCEN_STEP(v.w, g.w, ov.w);
        *reinterpret_cast<float4*>(o + t) = ov;
    }
#undef PCEN_STEP
}

extern "C" void kernel_launch(void* const* d_in, const int* in_sizes, int n_in,
                              void* d_out, int out_size)
{
    const float* mel = (const float*)d_in[0];
    const float* ls_ns = (const float*)d_in[1];
    const float* la_ns = (const float*)d_in[2];
    const float* ld_ns = (const float*)d_in[3];
    const float* lr_ns = (const float*)d_in[4];
    const float* ls_st = (const float*)d_in[5];
    const float* la_st = (const float*)d_in[6];
    const float* ld_st = (const float*)d_in[7];
    const float* lr_st = (const float*)d_in[8];
    const float* gate_temp = (const float*)d_in[9];
    float* out = (float*)d_out;

    const int gate_threads = NB * (NT / 4);             // 64000
    gate_kernel<<<(gate_threads + 127) / 128, 128>>>(mel, gate_temp);

    const int pcen_threads = NB * NM * NCH;             // 204800
    pcen_kernel<<<(pcen_threads + 255) / 256, 256>>>(
        mel, ls_ns, la_ns, ld_ns, lr_ns, ls_st, la_st, ld_st, lr_st, out);
}

// round 6
// speedup vs baseline: 1.3795x; 1.3795x over previous
#include <cuda_runtime.h>

#define NB 64
#define NM 80
#define NT 4000
#define NCH 20       // chunks per row
#define LCH 200      // chunk length (NT / NCH), multiple of 4
#define WARM 192     // warmup window; 0.95^192 ~ 5e-5

__device__ float g_gate[NB * NT];

__device__ __forceinline__ float clampf(float x, float lo, float hi) {
    return fminf(fmaxf(x, lo), hi);
}
__device__ __forceinline__ float sigmoidf(float x) {
    return 1.0f / (1.0f + __expf(-x));
}

// ---------------------------------------------------------------------------
// Kernel 1: spectral-flatness gate per (b, t). Thread handles 4 consecutive t.
// ---------------------------------------------------------------------------
__global__ void __launch_bounds__(128) gate_kernel(
    const float* __restrict__ mel,
    const float* __restrict__ gate_temp)
{
    int idx = blockIdx.x * blockDim.x + threadIdx.x;
    if (idx >= NB * (NT / 4)) return;
    int b  = idx / (NT / 4);
    int t4 = idx - b * (NT / 4);

    const float4* base = reinterpret_cast<const float4*>(mel) + (size_t)b * NM * (NT / 4) + t4;

    float sum[4]  = {0.f, 0.f, 0.f, 0.f};
    float low[4]  = {0.f, 0.f, 0.f, 0.f};
    float high[4] = {0.f, 0.f, 0.f, 0.f};
    float lp[4]   = {0.f, 0.f, 0.f, 0.f};

    #pragma unroll
    for (int g = 0; g < 4; ++g) {
        float p[4] = {1.f, 1.f, 1.f, 1.f};
        #pragma unroll
        for (int j = 0; j < 20; ++j) {
            const int m = g * 20 + j;
            float4 v = base[(size_t)m * (NT / 4)];
            float xv[4] = {v.x, v.y, v.z, v.w};
            #pragma unroll
            for (int k = 0; k < 4; ++k) {
                sum[k] += xv[k];
                p[k]   *= xv[k] + 1e-8f;
                if (m < 26)  low[k]  += xv[k];   // M//3 = 26
                if (m >= 53) high[k] += xv[k];   // 2*M//3 = 53 -> 27 channels
            }
        }
        #pragma unroll
        for (int k = 0; k < 4; ++k) lp[k] += __log2f(p[k]);
    }

    const float gt = gate_temp[0];
    float4 gout;
    float* go = &gout.x;
    #pragma unroll
    for (int k = 0; k < 4; ++k) {
        float arith = sum[k] * (1.0f / NM) + 1e-8f;
        float geo   = exp2f(lp[k] * (1.0f / NM));
        float sf    = clampf(__fdividef(geo, arith), 0.f, 1.f);
        float lo_   = low[k]  * (1.0f / 26.0f);
        float hi_   = high[k] * (1.0f / 27.0f);
        float tilt  = clampf(__fdividef(lo_, lo_ + hi_ + 1e-8f), 0.f, 1.f);
        float sfa   = sf + (1.0f - sf) * fmaxf(tilt - 0.6f, 0.f);
        go[k] = sigmoidf(gt * (sfa - 0.5f));
    }
    reinterpret_cast<float4*>(g_gate)[idx] = gout;
}

// ---------------------------------------------------------------------------
// Kernel 2: dual PCEN. Recurrence unrolled 4x in closed form so the
// cross-iteration dependency is a single FMA (4 cyc per 4 samples):
//   t1=a*x0+x1; t2=a*t1+x2; t3=a*t2+x3   (independent of sm)
//   sm_{+k} = a^k * sm + s * t_{k-1}
// ---------------------------------------------------------------------------
__global__ void __launch_bounds__(256) pcen_kernel(
    const float* __restrict__ mel,
    const float* __restrict__ ls_ns, const float* __restrict__ la_ns,
    const float* __restrict__ ld_ns, const float* __restrict__ lr_ns,
    const float* __restrict__ ls_st, const float* __restrict__ la_st,
    const float* __restrict__ ld_st, const float* __restrict__ lr_st,
    float* __restrict__ out)
{
    int tid = blockIdx.x * blockDim.x + threadIdx.x;
    if (tid >= NB * NM * NCH) return;
    int chunk = tid / (NB * NM);
    int row   = tid - chunk * (NB * NM);
    int b = row / NM;
    int m = row - b * NM;

    // Per-channel params
    const float s_ns  = clampf(sigmoidf(ls_ns[m]), 0.05f, 0.3f);
    const float a_ns  = 1.0f - s_ns;
    const float a2_ns = a_ns * a_ns;
    const float a3_ns = a2_ns * a_ns;
    const float a4_ns = a2_ns * a2_ns;
    const float al_ns = clampf(sigmoidf(la_ns[m]), 0.9f, 0.999f);
    const float d_ns  = clampf(__expf(ld_ns[m]), 0.5f, 5.0f);
    const float r_ns  = clampf(sigmoidf(lr_ns[m]), 0.05f, 0.25f);
    const float dp_ns = __powf(d_ns, r_ns);

    const float s_st  = clampf(sigmoidf(ls_st[m]), 0.05f, 0.3f);
    const float a_st  = 1.0f - s_st;
    const float a2_st = a_st * a_st;
    const float a3_st = a2_st * a_st;
    const float a4_st = a2_st * a2_st;
    const float al_st = clampf(sigmoidf(la_st[m]), 0.9f, 0.999f);
    const float d_st  = clampf(__expf(ld_st[m]), 0.001f, 0.1f);
    const float r_st  = clampf(sigmoidf(lr_st[m]), 0.05f, 0.25f);
    const float dp_st = __powf(d_st, r_st);

    const float* x  = mel + (size_t)row * NT;
    const float* gp = g_gate + (size_t)b * NT;
    float* o        = out + (size_t)row * NT;

    const int t0 = chunk * LCH;
    int tw = t0 - WARM;
    if (tw < 0) tw = 0;

    float sm_ns = x[tw];
    float sm_st = sm_ns;

    // Warmup: only the final state is needed -> 1 dependent FMA per 4 samples.
    for (int t = tw; t < t0; t += 4) {
        float4 v = *reinterpret_cast<const float4*>(x + t);
        float u1n = fmaf(a_ns, v.x, v.y);
        float u2n = fmaf(a_ns, u1n, v.z);
        float u3n = fmaf(a_ns, u2n, v.w);
        float u1s = fmaf(a_st, v.x, v.y);
        float u2s = fmaf(a_st, u1s, v.z);
        float u3s = fmaf(a_st, u2s, v.w);
        sm_ns = fmaf(a4_ns, sm_ns, s_ns * u3n);
        sm_st = fmaf(a4_st, sm_st, s_st * u3s);
    }

#define PCEN_OUT(smn, sms, xx, gg, oo) do {                            \
        float gn = __powf(1e-6f + (smn), -al_ns);                      \
        float on = __powf(fmaf((xx), gn, d_ns), r_ns) - dp_ns;         \
        float gs = __powf(1e-6f + (sms), -al_st);                      \
        float os = __powf(fmaf((xx), gs, d_st), r_st) - dp_st;         \
        (oo) = fmaf((gg), os - on, on);                                \
    } while (0)

    for (int t = t0; t < t0 + LCH; t += 4) {
        float4 v = *reinterpret_cast<const float4*>(x + t);
        float4 g = *reinterpret_cast<const float4*>(gp + t);

        // prefix combos (independent of sm)
        float u1n = fmaf(a_ns, v.x, v.y);
        float u2n = fmaf(a_ns, u1n, v.z);
        float u3n = fmaf(a_ns, u2n, v.w);
        float u1s = fmaf(a_st, v.x, v.y);
        float u2s = fmaf(a_st, u1s, v.z);
        float u3s = fmaf(a_st, u2s, v.w);

        // four states, each one FMA off the carried sm
        float n1 = fmaf(a_ns,  sm_ns, s_ns * v.x);
        float n2 = fmaf(a2_ns, sm_ns, s_ns * u1n);
        float n3 = fmaf(a3_ns, sm_ns, s_ns * u2n);
        float n4 = fmaf(a4_ns, sm_ns, s_ns * u3n);
        float s1 = fmaf(a_st,  sm_st, s_st * v.x);
        float s2 = fmaf(a2_st, sm_st, s_st * u1s);
        float s3 = fmaf(a3_st, sm_st, s_st * u2s);
        float s4 = fmaf(a4_st, sm_st, s_st * u3s);
        sm_ns = n4;
        sm_st = s4;

        float4 ov;
        PCEN_OUT(n1, s1, v.x, g.x, ov.x);
        PCEN_OUT(n2, s2, v.y, g.y, ov.y);
        PCEN_OUT(n3, s3, v.z, g.z, ov.z);
        PCEN_OUT(n4, s4, v.w, g.w, ov.w);
        *reinterpret_cast<float4*>(o + t) = ov;
    }
#undef PCEN_OUT
}

extern "C" void kernel_launch(void* const* d_in, const int* in_sizes, int n_in,
                              void* d_out, int out_size)
{
    const float* mel = (const float*)d_in[0];
    const float* ls_ns = (const float*)d_in[1];
    const float* la_ns = (const float*)d_in[2];
    const float* ld_ns = (const float*)d_in[3];
    const float* lr_ns = (const float*)d_in[4];
    const float* ls_st = (const float*)d_in[5];
    const float* la_st = (const float*)d_in[6];
    const float* ld_st = (const float*)d_in[7];
    const float* lr_st = (const float*)d_in[8];
    const float* gate_temp = (const float*)d_in[9];
    float* out = (float*)d_out;

    const int gate_threads = NB * (NT / 4);             // 64000
    gate_kernel<<<(gate_threads + 127) / 128, 128>>>(mel, gate_temp);

    const int pcen_threads = NB * NM * NCH;             // 102400
    pcen_kernel<<<(pcen_threads + 255) / 256, 256>>>(
        mel, ls_ns, la_ns, ld_ns, lr_ns, ls_st, la_st, ld_st, lr_st, out);
}